// round 1
// baseline (speedup 1.0000x reference)
#include <cuda_runtime.h>
#include <mma.h>
#include <math.h>
#include <stdint.h>

using namespace nvcuda;

// ---------------- problem constants ----------------
#define BB 8
#define T1C 32
#define T2C 32
#define JC 33          // T2+1
#define KSEG 9         // MAXSEG+1
#define NN 8448        // B*T1*J
#define EC 256
#define HC 512
#define UC 1024
#define GHC 2048       // 4*H
#define VC 8000
#define START_ID 8001
#define GIN_ROWS 2376          // KSEG*B*J
#define GIN_ROWS_PAD 2432      // padded to 19*128

// ---------------- device scratch (static globals; no runtime alloc) ----------------
__device__ float d_X1[NN * 1024];        // [h0 | h1] per row
__device__ float d_g[NN * GHC];          // gate pre-activations
__device__ float d_c0[NN * HC];
__device__ float d_c1[NN * HC];
__device__ float d_fco[NN * EC];         // h1 @ Wfc^T + bfc
__device__ float d_gin[GIN_ROWS_PAD * GHC];   // emb @ Wih0[:, :E]^T
__device__ float d_gctx[256 * GHC];           // ctx @ Wih0[:, E:E+H]^T + bih0 + bhh0
__device__ float d_ctx[256 * HC];             // enc_outs @ Wph^T + bph  (rows = b*32+t1)
__device__ float d_W1cat[GHC * 1024];         // [Wih1 | Whh1]
__device__ float d_hinit[2 * BB * HC];
__device__ float d_cinit[2 * BB * HC];
__device__ float d_cum[NN];
__device__ int   d_ginoff[GIN_ROWS_PAD];      // token*E row offsets into embed_w
__device__ int   d_ctxoff[256];               // row offsets into encoder_outs
__device__ int   d_tgttok[GIN_ROWS];          // target token per (k,b,j)

__device__ __forceinline__ float sigf(float x) { return 1.0f / (1.0f + expf(-x)); }

// ---------------- tiny prologue kernels ----------------
__global__ void tok_kernel(const int* __restrict__ prev) {
    int r = blockIdx.x * blockDim.x + threadIdx.x;
    if (r >= GIN_ROWS_PAD) return;
    if (r < GIN_ROWS) {
        int k = r / (BB * JC);
        int bj = r - k * (BB * JC);
        int b = bj / JC;
        int j = bj - b * JC;
        int pin = j + k - 1; if (pin > T2C - 1) pin = T2C - 1;
        int tin = (k == 0) ? START_ID : prev[b * T2C + pin];
        d_ginoff[r] = tin * EC;
        int pt = j + k; if (pt > T2C - 1) pt = T2C - 1;
        d_tgttok[r] = prev[b * T2C + pt];
    } else {
        d_ginoff[r] = 0;
    }
}

__global__ void ctxoff_kernel() {
    int r = threadIdx.x;  // 256 rows: r = b*T1 + t1
    if (r < 256) {
        int b = r / T1C, t1 = r - b * T1C;
        d_ctxoff[r] = t1 * (BB * UC) + b * UC;   // encoder_outs[t1, b, :]
    }
}

__global__ void hcinit_kernel(const float* __restrict__ ench, const float* __restrict__ encc,
                              const float* __restrict__ Wph, const float* __restrict__ bph,
                              const float* __restrict__ Wpc, const float* __restrict__ bpc) {
    int idx = blockIdx.x * blockDim.x + threadIdx.x;  // 2*8*512 = 8192
    if (idx >= 2 * BB * HC) return;
    int l = idx / (BB * HC);
    int b = (idx / HC) % BB;
    int h = idx % HC;
    const float4* eh = (const float4*)(ench + l * BB * UC + b * UC);
    const float4* ec = (const float4*)(encc + l * BB * UC + b * UC);
    const float4* wh = (const float4*)(Wph + (size_t)h * UC);
    const float4* wc = (const float4*)(Wpc + (size_t)h * UC);
    float sh = 0.f, sc = 0.f;
    for (int u = 0; u < UC / 4; u++) {
        float4 a = eh[u], w = wh[u];
        sh += a.x * w.x + a.y * w.y + a.z * w.z + a.w * w.w;
        float4 a2 = ec[u], w2 = wc[u];
        sc += a2.x * w2.x + a2.y * w2.y + a2.z * w2.z + a2.w * w2.w;
    }
    d_hinit[idx] = sh + bph[h];
    d_cinit[idx] = sc + bpc[h];
}

__global__ void w1cat_kernel(const float* __restrict__ Wih1, const float* __restrict__ Whh1) {
    int idx = blockIdx.x * blockDim.x + threadIdx.x;  // 2048*1024
    if (idx >= GHC * 1024) return;
    int m = idx >> 10, c = idx & 1023;
    d_W1cat[idx] = (c < HC) ? Wih1[(size_t)m * HC + c] : Whh1[(size_t)m * HC + (c - HC)];
}

__global__ void initX_kernel() {
    int idx = blockIdx.x * blockDim.x + threadIdx.x;  // N*512
    if (idx >= NN * HC) return;
    int n = idx >> 9, h = idx & 511;
    int b = n / (T1C * JC);
    d_X1[(size_t)n * 1024 + h]       = d_hinit[b * HC + h];
    d_X1[(size_t)n * 1024 + 512 + h] = d_hinit[BB * HC + b * HC + h];
    d_c0[idx] = d_cinit[b * HC + h];
    d_c1[idx] = d_cinit[BB * HC + b * HC + h];
    if (h == 0) d_cum[n] = 0.f;
}

// ---------------- LSTM elementwise cell ----------------
__global__ void cell_kernel(const float* __restrict__ g, float* __restrict__ c,
                            float* __restrict__ hout /* stride 1024 rows */) {
    int idx = blockIdx.x * blockDim.x + threadIdx.x;  // N*512
    if (idx >= NN * HC) return;
    int n = idx >> 9, h = idx & 511;
    const float* gr = g + (size_t)n * GHC + h;
    float i_ = gr[0], f_ = gr[512], gg = gr[1024], o_ = gr[1536];
    float cv = sigf(f_) * c[idx] + sigf(i_) * tanhf(gg);
    c[idx] = cv;
    hout[(size_t)n * 1024 + h] = sigf(o_) * tanhf(cv);
}

// ---------------- generic TN GEMM (wmma tf32): C[m,n] = sum_k A[m,k]*B[n,k] + epi ----------------
// EPI: 0 none, 1 +e1[n], 2 +e1[n]+e2[n], 3 +gin[row(m,kstep)] + gctx[row(m)]
template <int EPI, bool GATHER>
__launch_bounds__(256)
__global__ void gemm_tn(const float* __restrict__ A, int lda,
                        const float* __restrict__ Bm, int ldb,
                        float* __restrict__ C, int ldc, int K,
                        const int* __restrict__ rowoff,
                        const float* __restrict__ e1, const float* __restrict__ e2,
                        int kstep) {
    __shared__ float smem[8192];       // union: [A 128x40 | B 64x40] then C 128x64
    float* sA = smem;                  // 5120
    float* sB = smem + 5120;           // 2560
    int tid = threadIdx.x;
    int m0 = blockIdx.y * 128, n0 = blockIdx.x * 64;
    int wid = tid >> 5;
    int wm = wid & 3, wn = wid >> 2;

    wmma::fragment<wmma::accumulator, 16, 16, 8, float> acc[2][2];
#pragma unroll
    for (int mi = 0; mi < 2; mi++)
#pragma unroll
        for (int ni = 0; ni < 2; ni++) wmma::fill_fragment(acc[mi][ni], 0.0f);

    for (int k0 = 0; k0 < K; k0 += 32) {
#pragma unroll
        for (int i = 0; i < 4; i++) {            // A tile 128x32
            int idx = tid + i * 256;
            int r = idx >> 3, c4 = idx & 7;
            const float* src = GATHER ? (A + rowoff[m0 + r] + k0 + c4 * 4)
                                      : (A + (size_t)(m0 + r) * lda + k0 + c4 * 4);
            *(float4*)(sA + r * 40 + c4 * 4) = *(const float4*)src;
        }
#pragma unroll
        for (int i = 0; i < 2; i++) {            // B tile 64x32
            int idx = tid + i * 256;
            int r = idx >> 3, c4 = idx & 7;
            *(float4*)(sB + r * 40 + c4 * 4) =
                *(const float4*)(Bm + (size_t)(n0 + r) * ldb + k0 + c4 * 4);
        }
        __syncthreads();
#pragma unroll
        for (int kk = 0; kk < 4; kk++) {
            wmma::fragment<wmma::matrix_a, 16, 16, 8, wmma::precision::tf32, wmma::row_major> af[2];
            wmma::fragment<wmma::matrix_b, 16, 16, 8, wmma::precision::tf32, wmma::col_major> bf[2];
#pragma unroll
            for (int mi = 0; mi < 2; mi++) {
                wmma::load_matrix_sync(af[mi], sA + (wm * 32 + mi * 16) * 40 + kk * 8, 40);
#pragma unroll
                for (int t = 0; t < af[mi].num_elements; t++) af[mi].x[t] = wmma::__float_to_tf32(af[mi].x[t]);
            }
#pragma unroll
            for (int ni = 0; ni < 2; ni++) {
                wmma::load_matrix_sync(bf[ni], sB + (wn * 32 + ni * 16) * 40 + kk * 8, 40);
#pragma unroll
                for (int t = 0; t < bf[ni].num_elements; t++) bf[ni].x[t] = wmma::__float_to_tf32(bf[ni].x[t]);
            }
#pragma unroll
            for (int mi = 0; mi < 2; mi++)
#pragma unroll
                for (int ni = 0; ni < 2; ni++)
                    wmma::mma_sync(acc[mi][ni], af[mi], bf[ni], acc[mi][ni]);
        }
        __syncthreads();
    }

    float* sC = smem;  // 128x64 overlay
#pragma unroll
    for (int mi = 0; mi < 2; mi++)
#pragma unroll
        for (int ni = 0; ni < 2; ni++)
            wmma::store_matrix_sync(sC + (wm * 32 + mi * 16) * 64 + wn * 32 + ni * 16,
                                    acc[mi][ni], 64, wmma::mem_row_major);
    __syncthreads();

#pragma unroll
    for (int i = 0; i < 8; i++) {
        int idx = tid + i * 256;    // 2048 float4
        int r = idx >> 4, c4 = idx & 15;
        float4 v = *(float4*)(sC + r * 64 + c4 * 4);
        int m = m0 + r;
        int nb = n0 + c4 * 4;
        if (EPI == 1) {
            v.x += e1[nb]; v.y += e1[nb + 1]; v.z += e1[nb + 2]; v.w += e1[nb + 3];
        } else if (EPI == 2) {
            v.x += e1[nb] + e2[nb]; v.y += e1[nb + 1] + e2[nb + 1];
            v.z += e1[nb + 2] + e2[nb + 2]; v.w += e1[nb + 3] + e2[nb + 3];
        } else if (EPI == 3) {
            int b = m / (T1C * JC);
            int rem = m - b * (T1C * JC);
            int t1 = rem / JC;
            int j = rem - t1 * JC;
            const float* gi = e1 + (size_t)((kstep * BB + b) * JC + j) * GHC + nb;
            const float* gc = e2 + (size_t)(b * T1C + t1) * GHC + nb;
            float4 a1 = *(const float4*)gi;
            float4 a2 = *(const float4*)gc;
            v.x += a1.x + a2.x; v.y += a1.y + a2.y; v.z += a1.z + a2.z; v.w += a1.w + a2.w;
        }
        *(float4*)(C + (size_t)m * ldc + nb) = v;
    }
}

// ---------------- fused Wout GEMM + online logsumexp + output ----------------
// block = 64 rows x full 8000 cols. A (64x256) resident in smem.
#define WOUT_SMEM_FLOATS (16896 + 4608 + 4608 + 64 * 4 + 64)
__launch_bounds__(256)
__global__ void wout_lse(const float* __restrict__ fco, const float* __restrict__ Wout,
                         const float* __restrict__ bout, const int* __restrict__ tgttok,
                         float* __restrict__ cum, float* __restrict__ outp, int kstep) {
    extern __shared__ float sm[];
    float* A_s = sm;                 // 64 x 264
    float* B_s = sm + 16896;         // 64 x 72
    float* C_s = B_s + 4608;         // 64 x 72
    float* rM = C_s + 4608;
    float* rS = rM + 64;
    float* rE = rS + 64;
    float* rT = rE + 64;
    int* rTgt = (int*)(rT + 64);

    int tid = threadIdx.x;
    int m0 = blockIdx.x * 64;

#pragma unroll
    for (int i = 0; i < 16; i++) {   // A: 64 x 256 = 4096 float4
        int idx = tid + i * 256;
        int r = idx >> 6, c4 = idx & 63;
        *(float4*)(A_s + r * 264 + c4 * 4) = *(const float4*)(fco + (size_t)(m0 + r) * EC + c4 * 4);
    }
    if (tid < 64) {
        int n = m0 + tid;
        int b = n / (T1C * JC);
        int rem = n - b * (T1C * JC);
        int j = rem % JC;
        rTgt[tid] = tgttok[(kstep * BB + b) * JC + j];
        rM[tid] = -1e30f; rS[tid] = 0.f; rE[tid] = 0.f; rT[tid] = 0.f;
    }
    __syncthreads();

    int wid = tid >> 5;
    int wm = wid & 1, wn = wid >> 1;

    for (int nc = 0; nc < VC / 64; nc++) {
        int n0v = nc * 64;
        wmma::fragment<wmma::accumulator, 16, 16, 8, float> acc[2];
        wmma::fill_fragment(acc[0], 0.0f);
        wmma::fill_fragment(acc[1], 0.0f);
        for (int k0 = 0; k0 < EC; k0 += 64) {
#pragma unroll
            for (int i = 0; i < 4; i++) {        // B subtile 64x64
                int idx = tid + i * 256;
                int r = idx >> 4, c4 = idx & 15;
                *(float4*)(B_s + r * 72 + c4 * 4) =
                    *(const float4*)(Wout + (size_t)(n0v + r) * EC + k0 + c4 * 4);
            }
            __syncthreads();
#pragma unroll
            for (int kk = 0; kk < 8; kk++) {
                wmma::fragment<wmma::matrix_a, 16, 16, 8, wmma::precision::tf32, wmma::row_major> af[2];
                wmma::fragment<wmma::matrix_b, 16, 16, 8, wmma::precision::tf32, wmma::col_major> bf;
#pragma unroll
                for (int mi = 0; mi < 2; mi++) {
                    wmma::load_matrix_sync(af[mi], A_s + (wm * 32 + mi * 16) * 264 + k0 + kk * 8, 264);
#pragma unroll
                    for (int t = 0; t < af[mi].num_elements; t++) af[mi].x[t] = wmma::__float_to_tf32(af[mi].x[t]);
                }
                wmma::load_matrix_sync(bf, B_s + (wn * 16) * 72 + kk * 8, 72);
#pragma unroll
                for (int t = 0; t < bf.num_elements; t++) bf.x[t] = wmma::__float_to_tf32(bf.x[t]);
                wmma::mma_sync(acc[0], af[0], bf, acc[0]);
                wmma::mma_sync(acc[1], af[1], bf, acc[1]);
            }
            __syncthreads();
        }
        wmma::store_matrix_sync(C_s + (wm * 32 + 0) * 72 + wn * 16, acc[0], 72, wmma::mem_row_major);
        wmma::store_matrix_sync(C_s + (wm * 32 + 16) * 72 + wn * 16, acc[1], 72, wmma::mem_row_major);
        __syncthreads();

        {   // online logsumexp scan: 4 lanes per row, 16 cols each
            int r = tid >> 2, q = tid & 3;
            float lm = -1e30f, ls = 0.f;
            int tgt = rTgt[r];
#pragma unroll
            for (int c = 0; c < 16; c++) {
                int col = q * 16 + c;
                int gcol = n0v + col;
                float l = C_s[r * 72 + col] + bout[gcol];
                if (gcol == 2) rE[r] = l;
                if (gcol == tgt) rT[r] = l;
                if (l <= lm) {
                    ls += __expf(l - lm);
                } else {
                    ls = ls * __expf(lm - l) + 1.0f;
                    lm = l;
                }
            }
#pragma unroll
            for (int off = 1; off < 4; off <<= 1) {
                float om = __shfl_xor_sync(0xffffffffu, lm, off);
                float os = __shfl_xor_sync(0xffffffffu, ls, off);
                float nm = fmaxf(lm, om);
                ls = ls * __expf(lm - nm) + os * __expf(om - nm);
                lm = nm;
            }
            if (q == 0) {
                float M = rM[r], S = rS[r];
                float nm = fmaxf(M, lm);
                rS[r] = S * __expf(M - nm) + ls * __expf(lm - nm);
                rM[r] = nm;
            }
        }
        __syncthreads();
    }

    if (tid < 64) {
        int n = m0 + tid;
        float lse = rM[tid] + logf(rS[tid]);
        int j = n % JC;
        bool valid = (j + kstep) <= T2C;
        float cv = cum[n];
        outp[(size_t)n * KSEG + kstep] = valid ? (cv + rE[tid] - lse) : -1e9f;
        cum[n] = cv + rT[tid] - lse;
    }
}

// ---------------- host launch ----------------
static inline float* fsym(const void* sym) {
    void* p = nullptr;
    cudaGetSymbolAddress(&p, sym);
    return (float*)p;
}
static inline int* isym(const void* sym) {
    void* p = nullptr;
    cudaGetSymbolAddress(&p, sym);
    return (int*)p;
}

extern "C" void kernel_launch(void* const* d_in, const int* in_sizes, int n_in,
                              void* d_out, int out_size) {
    const int*   prev   = (const int*)d_in[0];
    const float* encO   = (const float*)d_in[1];
    const float* encH   = (const float*)d_in[2];
    const float* encC   = (const float*)d_in[3];
    const float* embed  = (const float*)d_in[4];
    const float* Wph    = (const float*)d_in[5];
    const float* bph    = (const float*)d_in[6];
    const float* Wpc    = (const float*)d_in[7];
    const float* bpc    = (const float*)d_in[8];
    const float* Wih0   = (const float*)d_in[9];
    const float* Whh0   = (const float*)d_in[10];
    const float* bih0   = (const float*)d_in[11];
    const float* bhh0   = (const float*)d_in[12];
    const float* Wih1   = (const float*)d_in[13];
    const float* Whh1   = (const float*)d_in[14];
    const float* bih1   = (const float*)d_in[15];
    const float* bhh1   = (const float*)d_in[16];
    const float* Wfc    = (const float*)d_in[17];
    const float* bfc    = (const float*)d_in[18];
    const float* Wout   = (const float*)d_in[19];
    const float* bout   = (const float*)d_in[20];
    float* outp = (float*)d_out;

    float* pX1   = fsym(d_X1);
    float* pg    = fsym(d_g);
    float* pc0   = fsym(d_c0);
    float* pc1   = fsym(d_c1);
    float* pfco  = fsym(d_fco);
    float* pgin  = fsym(d_gin);
    float* pgctx = fsym(d_gctx);
    float* pctx  = fsym(d_ctx);
    float* pW1   = fsym(d_W1cat);
    float* pcum  = fsym(d_cum);
    int*   pgoff = isym(d_ginoff);
    int*   pcoff = isym(d_ctxoff);
    int*   ptgt  = isym(d_tgttok);

    const int WOUT_SMEM_BYTES = WOUT_SMEM_FLOATS * 4;
    cudaFuncSetAttribute(wout_lse, cudaFuncAttributeMaxDynamicSharedMemorySize, WOUT_SMEM_BYTES);

    // prologue
    tok_kernel<<<(GIN_ROWS_PAD + 255) / 256, 256>>>(prev);
    ctxoff_kernel<<<1, 256>>>();
    hcinit_kernel<<<(2 * BB * HC + 255) / 256, 256>>>(encH, encC, Wph, bph, Wpc, bpc);
    w1cat_kernel<<<(GHC * 1024) / 256, 256>>>(Wih1, Whh1);
    initX_kernel<<<(NN * HC) / 256, 256>>>();

    // ctx = encO @ Wph^T + bph   (gathered rows), M=256, N=512, K=1024
    gemm_tn<1, true><<<dim3(512 / 64, 256 / 128), 256>>>(
        encO, 0, Wph, UC, pctx, HC, UC, pcoff, bph, nullptr, 0);
    // gctx = ctx @ Wih0[:,E:E+H]^T + bih0 + bhh0   M=256, N=2048, K=512
    gemm_tn<2, false><<<dim3(GHC / 64, 256 / 128), 256>>>(
        pctx, HC, Wih0 + EC, EC + HC, pgctx, GHC, HC, nullptr, bih0, bhh0, 0);
    // gin = emb @ Wih0[:, :E]^T   M=2432(pad), N=2048, K=256
    gemm_tn<0, true><<<dim3(GHC / 64, GIN_ROWS_PAD / 128), 256>>>(
        embed, 0, Wih0, EC + HC, pgin, GHC, EC, pgoff, nullptr, nullptr, 0);

    for (int k = 0; k < KSEG; k++) {
        // g0 = h0 @ Whh0^T + gin + gctx
        gemm_tn<3, false><<<dim3(GHC / 64, NN / 128), 256>>>(
            pX1, 1024, Whh0, HC, pg, GHC, HC, nullptr, pgin, pgctx, k);
        cell_kernel<<<(NN * HC) / 256, 256>>>(pg, pc0, pX1);
        // g1 = [h0n|h1] @ [Wih1|Whh1]^T + bih1 + bhh1
        gemm_tn<2, false><<<dim3(GHC / 64, NN / 128), 256>>>(
            pX1, 1024, pW1, 1024, pg, GHC, 1024, nullptr, bih1, bhh1, 0);
        cell_kernel<<<(NN * HC) / 256, 256>>>(pg, pc1, pX1 + 512);
        // fco = h1 @ Wfc^T + bfc
        gemm_tn<1, false><<<dim3(EC / 64, NN / 128), 256>>>(
            pX1 + 512, 1024, Wfc, HC, pfco, EC, HC, nullptr, bfc, nullptr, 0);
        // logits + logsumexp + output + cum update
        wout_lse<<<NN / 64, 256, WOUT_SMEM_BYTES>>>(pfco, Wout, bout, ptgt, pcum, outp, k);
    }
}

// round 2
// speedup vs baseline: 3.1174x; 3.1174x over previous
#include <cuda_runtime.h>
#include <cuda_bf16.h>
#include <mma.h>
#include <math.h>
#include <stdint.h>

using namespace nvcuda;

// ---------------- problem constants ----------------
#define BB 8
#define T1C 32
#define T2C 32
#define JC 33          // T2+1
#define KSEG 9         // MAXSEG+1
#define NN 8448        // B*T1*J
#define EC 256
#define HC 512
#define UC 1024
#define GHC 2048       // 4*H
#define VC 8000
#define START_ID 8001
#define GIN_ROWS 2376          // KSEG*B*J
#define GIN_ROWS_PAD 2432      // 19*128

typedef __nv_bfloat16 bf16;
typedef __nv_bfloat162 bf162;

// ---------------- device scratch ----------------
__device__ bf16  d_X1[NN * 1024];          // [h0 | h1] per row (bf16)
__device__ float d_g[NN * GHC];            // gate pre-activations (fp32)
__device__ float d_c0[NN * HC];
__device__ float d_c1[NN * HC];
__device__ bf16  d_fco[NN * EC];           // h1 @ Wfc^T + bfc (bf16)
__device__ float d_gin[GIN_ROWS_PAD * GHC];
__device__ float d_gctx[256 * GHC];
__device__ bf16  d_ctxb[256 * HC];
__device__ float d_hinit[2 * BB * HC];
__device__ float d_cinit[2 * BB * HC];
__device__ float d_cum[NN];
__device__ int   d_ginoff[GIN_ROWS_PAD];
__device__ int   d_ctxoff[256];
__device__ int   d_tgttok[GIN_ROWS];
// bf16 weight copies
__device__ bf16 d_Whh0b[GHC * HC];
__device__ bf16 d_W1catb[GHC * 1024];
__device__ bf16 d_Wfcb[EC * HC];
__device__ bf16 d_Woutb[VC * EC];
__device__ bf16 d_embb[(VC + 2) * EC];
__device__ bf16 d_Wih0b[GHC * (EC + HC)];
__device__ bf16 d_Wphb[HC * UC];
__device__ bf16 d_encOb[T1C * BB * UC];

__device__ __forceinline__ float sigf(float x) { return 1.0f / (1.0f + expf(-x)); }

__device__ __forceinline__ void cpa16(void* dst, const void* src) {
    uint32_t d = (uint32_t)__cvta_generic_to_shared(dst);
    asm volatile("cp.async.cg.shared.global [%0], [%1], 16;\n" :: "r"(d), "l"(src));
}
__device__ __forceinline__ void cpa_commit() { asm volatile("cp.async.commit_group;\n"); }
template <int N> __device__ __forceinline__ void cpa_wait() {
    asm volatile("cp.async.wait_group %0;\n" :: "n"(N));
}

// ---------------- prologue kernels ----------------
__global__ void cvt_kernel(const float* __restrict__ src, bf16* __restrict__ dst, int n4) {
    int i = blockIdx.x * blockDim.x + threadIdx.x;
    if (i >= n4) return;
    float4 v = ((const float4*)src)[i];
    bf162* d = (bf162*)dst + i * 2;
    d[0] = __floats2bfloat162_rn(v.x, v.y);
    d[1] = __floats2bfloat162_rn(v.z, v.w);
}

__global__ void w1cat_kernel(const float* __restrict__ Wih1, const float* __restrict__ Whh1) {
    int idx = blockIdx.x * blockDim.x + threadIdx.x;
    if (idx >= GHC * 1024) return;
    int m = idx >> 10, c = idx & 1023;
    float v = (c < HC) ? Wih1[(size_t)m * HC + c] : Whh1[(size_t)m * HC + (c - HC)];
    d_W1catb[idx] = __float2bfloat16(v);
}

__global__ void tok_kernel(const int* __restrict__ prev) {
    int r = blockIdx.x * blockDim.x + threadIdx.x;
    if (r >= GIN_ROWS_PAD) return;
    if (r < GIN_ROWS) {
        int k = r / (BB * JC);
        int bj = r - k * (BB * JC);
        int b = bj / JC;
        int j = bj - b * JC;
        int pin = j + k - 1; if (pin > T2C - 1) pin = T2C - 1;
        int tin = (k == 0) ? START_ID : prev[b * T2C + pin];
        d_ginoff[r] = tin * EC;
        int pt = j + k; if (pt > T2C - 1) pt = T2C - 1;
        d_tgttok[r] = prev[b * T2C + pt];
    } else {
        d_ginoff[r] = 0;
    }
}

__global__ void ctxoff_kernel() {
    int r = threadIdx.x;
    if (r < 256) {
        int b = r / T1C, t1 = r - b * T1C;
        d_ctxoff[r] = t1 * (BB * UC) + b * UC;
    }
}

__global__ void hcinit_kernel(const float* __restrict__ ench, const float* __restrict__ encc,
                              const float* __restrict__ Wph, const float* __restrict__ bph,
                              const float* __restrict__ Wpc, const float* __restrict__ bpc) {
    int idx = blockIdx.x * blockDim.x + threadIdx.x;
    if (idx >= 2 * BB * HC) return;
    int l = idx / (BB * HC);
    int b = (idx / HC) % BB;
    int h = idx % HC;
    const float4* eh = (const float4*)(ench + l * BB * UC + b * UC);
    const float4* ec = (const float4*)(encc + l * BB * UC + b * UC);
    const float4* wh = (const float4*)(Wph + (size_t)h * UC);
    const float4* wc = (const float4*)(Wpc + (size_t)h * UC);
    float sh = 0.f, sc = 0.f;
    for (int u = 0; u < UC / 4; u++) {
        float4 a = eh[u], w = wh[u];
        sh += a.x * w.x + a.y * w.y + a.z * w.z + a.w * w.w;
        float4 a2 = ec[u], w2 = wc[u];
        sc += a2.x * w2.x + a2.y * w2.y + a2.z * w2.z + a2.w * w2.w;
    }
    d_hinit[idx] = sh + bph[h];
    d_cinit[idx] = sc + bpc[h];
}

__global__ void initX_kernel() {
    int idx = blockIdx.x * blockDim.x + threadIdx.x;
    if (idx >= NN * HC) return;
    int n = idx >> 9, h = idx & 511;
    int b = n / (T1C * JC);
    d_X1[(size_t)n * 1024 + h]       = __float2bfloat16(d_hinit[b * HC + h]);
    d_X1[(size_t)n * 1024 + 512 + h] = __float2bfloat16(d_hinit[BB * HC + b * HC + h]);
    d_c0[idx] = d_cinit[b * HC + h];
    d_c1[idx] = d_cinit[BB * HC + b * HC + h];
    if (h == 0) d_cum[n] = 0.f;
}

// ---------------- LSTM elementwise cell ----------------
__global__ void cell_kernel(const float* __restrict__ g, float* __restrict__ c,
                            bf16* __restrict__ hout /* stride 1024 rows */) {
    int idx = blockIdx.x * blockDim.x + threadIdx.x;
    if (idx >= NN * HC) return;
    int n = idx >> 9, h = idx & 511;
    const float* gr = g + (size_t)n * GHC + h;
    float i_ = gr[0], f_ = gr[512], gg = gr[1024], o_ = gr[1536];
    float cv = sigf(f_) * c[idx] + sigf(i_) * tanhf(gg);
    c[idx] = cv;
    hout[(size_t)n * 1024 + h] = __float2bfloat16(sigf(o_) * tanhf(cv));
}

// ---------------- bf16 TN GEMM, 128x128 tiles, double-buffered cp.async ----------------
// C[m,n] = sum_k A[m,k] * B[n,k] + epi
// EPI: 0 none, 1 +e1[n], 2 +e1[n]+e2[n], 3 +gin[row(m,kstep),n] + gctx[row(m),n]
// OBF: write bf16 output instead of fp32
#define GSM_BYTES 67584    // max(2*2*128*48*2, 128*132*4)
template <int EPI, bool GATHER, bool OBF>
__launch_bounds__(256)
__global__ void gemm_bf(const bf16* __restrict__ A, int lda,
                        const bf16* __restrict__ Bm, int ldb,
                        void* __restrict__ Cv, int ldc, int K,
                        const int* __restrict__ rowoff,
                        const float* __restrict__ e1, const float* __restrict__ e2,
                        int kstep) {
    extern __shared__ char smraw[];
    bf16* sA = (bf16*)smraw;                 // [2][128*48]
    bf16* sB = sA + 2 * 128 * 48;            // [2][128*48]
    float* sC = (float*)smraw;               // 128*132 overlay

    int tid = threadIdx.x;
    int m0 = blockIdx.y * 128, n0 = blockIdx.x * 128;
    int wid = tid >> 5;
    int wm = wid & 1, wn = wid >> 1;         // 2 x 4 warp grid; warp tile 64(m) x 32(n)

    wmma::fragment<wmma::accumulator, 16, 16, 16, float> acc[4][2];
#pragma unroll
    for (int mi = 0; mi < 4; mi++)
#pragma unroll
        for (int ni = 0; ni < 2; ni++) wmma::fill_fragment(acc[mi][ni], 0.0f);

    int nk = K >> 5;

    // stage-issue lambda substitute (macro-free, inlined twice)
#define GEMM_ISSUE(S)                                                                    \
    {                                                                                    \
        int buf_ = (S) & 1;                                                              \
        int k0_ = (S) << 5;                                                              \
        _Pragma("unroll")                                                                \
        for (int i_ = 0; i_ < 2; i_++) {                                                 \
            int idx_ = tid + i_ * 256;                                                   \
            int r_ = idx_ >> 2, c_ = idx_ & 3;                                           \
            const bf16* src_ = GATHER ? (A + rowoff[m0 + r_] + k0_ + c_ * 8)             \
                                      : (A + (size_t)(m0 + r_) * lda + k0_ + c_ * 8);    \
            cpa16(sA + buf_ * (128 * 48) + r_ * 48 + c_ * 8, src_);                      \
        }                                                                                \
        _Pragma("unroll")                                                                \
        for (int i_ = 0; i_ < 2; i_++) {                                                 \
            int idx_ = tid + i_ * 256;                                                   \
            int r_ = idx_ >> 2, c_ = idx_ & 3;                                           \
            cpa16(sB + buf_ * (128 * 48) + r_ * 48 + c_ * 8,                             \
                  Bm + (size_t)(n0 + r_) * ldb + k0_ + c_ * 8);                          \
        }                                                                                \
        cpa_commit();                                                                    \
    }

    GEMM_ISSUE(0);
    for (int s = 0; s < nk; s++) {
        __syncthreads();                 // prev-stage compute fully done before overwrite
        if (s + 1 < nk) {
            GEMM_ISSUE(s + 1);
            cpa_wait<1>();
        } else {
            cpa_wait<0>();
        }
        __syncthreads();
        int buf = s & 1;
        const bf16* a_base = sA + buf * (128 * 48);
        const bf16* b_base = sB + buf * (128 * 48);
#pragma unroll
        for (int kk = 0; kk < 2; kk++) {
            wmma::fragment<wmma::matrix_a, 16, 16, 16, bf16, wmma::row_major> af[4];
            wmma::fragment<wmma::matrix_b, 16, 16, 16, bf16, wmma::col_major> bfr[2];
#pragma unroll
            for (int mi = 0; mi < 4; mi++)
                wmma::load_matrix_sync(af[mi], a_base + (wm * 64 + mi * 16) * 48 + kk * 16, 48);
#pragma unroll
            for (int ni = 0; ni < 2; ni++)
                wmma::load_matrix_sync(bfr[ni], b_base + (wn * 32 + ni * 16) * 48 + kk * 16, 48);
#pragma unroll
            for (int mi = 0; mi < 4; mi++)
#pragma unroll
                for (int ni = 0; ni < 2; ni++)
                    wmma::mma_sync(acc[mi][ni], af[mi], bfr[ni], acc[mi][ni]);
        }
    }
    __syncthreads();
#pragma unroll
    for (int mi = 0; mi < 4; mi++)
#pragma unroll
        for (int ni = 0; ni < 2; ni++)
            wmma::store_matrix_sync(sC + (wm * 64 + mi * 16) * 132 + wn * 32 + ni * 16,
                                    acc[mi][ni], 132, wmma::mem_row_major);
    __syncthreads();

#pragma unroll
    for (int i = 0; i < 16; i++) {       // 128x128 = 4096 float4
        int idx = tid + i * 256;
        int r = idx >> 5, c4 = idx & 31;
        float4 v = *(float4*)(sC + r * 132 + c4 * 4);
        int m = m0 + r;
        int nb = n0 + c4 * 4;
        if (EPI == 1) {
            v.x += e1[nb]; v.y += e1[nb + 1]; v.z += e1[nb + 2]; v.w += e1[nb + 3];
        } else if (EPI == 2) {
            v.x += e1[nb] + e2[nb]; v.y += e1[nb + 1] + e2[nb + 1];
            v.z += e1[nb + 2] + e2[nb + 2]; v.w += e1[nb + 3] + e2[nb + 3];
        } else if (EPI == 3) {
            int b = m / (T1C * JC);
            int rem = m - b * (T1C * JC);
            int t1 = rem / JC;
            int j = rem - t1 * JC;
            const float* gi = e1 + (size_t)((kstep * BB + b) * JC + j) * GHC + nb;
            const float* gc = e2 + (size_t)(b * T1C + t1) * GHC + nb;
            float4 a1 = *(const float4*)gi;
            float4 a2 = *(const float4*)gc;
            v.x += a1.x + a2.x; v.y += a1.y + a2.y; v.z += a1.z + a2.z; v.w += a1.w + a2.w;
        }
        if (OBF) {
            bf162* p = (bf162*)((bf16*)Cv + (size_t)m * ldc + nb);
            p[0] = __floats2bfloat162_rn(v.x, v.y);
            p[1] = __floats2bfloat162_rn(v.z, v.w);
        } else {
            *(float4*)((float*)Cv + (size_t)m * ldc + nb) = v;
        }
    }
#undef GEMM_ISSUE
}

// ---------------- fused Wout GEMM (bf16) + online logsumexp ----------------
// block = 64 rows x full 8000 vocab. A resident, B double-buffered 64x256 chunks.
#define WA_STRIDE 264
#define WB_STRIDE 264
#define WOUT_SMEM_BYTES (64 * WA_STRIDE * 2 + 2 * 64 * WB_STRIDE * 2 + 64 * 72 * 4 + 64 * 5 * 4)
__launch_bounds__(256)
__global__ void wout_lse(const bf16* __restrict__ fco, const bf16* __restrict__ Wout,
                         const float* __restrict__ bout, const int* __restrict__ tgttok,
                         float* __restrict__ cum, float* __restrict__ outp, int kstep) {
    extern __shared__ char smraw[];
    bf16* A_s = (bf16*)smraw;                         // 64 x 264
    bf16* B_s = A_s + 64 * WA_STRIDE;                 // 2 x 64 x 264
    float* C_s = (float*)(B_s + 2 * 64 * WB_STRIDE);  // 64 x 72
    float* rM = C_s + 64 * 72;
    float* rS = rM + 64;
    float* rE = rS + 64;
    float* rT = rE + 64;
    int* rTgt = (int*)(rT + 64);

    int tid = threadIdx.x;
    int m0 = blockIdx.x * 64;

    // A: 64 x 256 bf16 = 2048 16B chunks
#pragma unroll
    for (int i = 0; i < 8; i++) {
        int idx = tid + i * 256;
        int r = idx >> 5, c = idx & 31;
        *(uint4*)(A_s + r * WA_STRIDE + c * 8) = *(const uint4*)(fco + (size_t)(m0 + r) * EC + c * 8);
    }
    if (tid < 64) {
        int n = m0 + tid;
        int b = n / (T1C * JC);
        int rem = n - b * (T1C * JC);
        int j = rem % JC;
        rTgt[tid] = tgttok[(kstep * BB + b) * JC + j];
        rM[tid] = -1e30f; rS[tid] = 0.f; rE[tid] = 0.f; rT[tid] = 0.f;
    }

    int wid = tid >> 5;
    int wm = wid & 1, wn = wid >> 1;   // warp tile 32(m) x 16(n)

#define WOUT_ISSUE(S)                                                                  \
    {                                                                                  \
        int buf_ = (S) & 1;                                                            \
        _Pragma("unroll")                                                              \
        for (int i_ = 0; i_ < 8; i_++) {                                               \
            int idx_ = tid + i_ * 256;                                                 \
            int r_ = idx_ >> 5, c_ = idx_ & 31;                                        \
            cpa16(B_s + buf_ * (64 * WB_STRIDE) + r_ * WB_STRIDE + c_ * 8,             \
                  Wout + (size_t)((S) * 64 + r_) * EC + c_ * 8);                       \
        }                                                                              \
        cpa_commit();                                                                  \
    }

    WOUT_ISSUE(0);
    const int NCC = VC / 64;  // 125
    for (int nc = 0; nc < NCC; nc++) {
        if (nc + 1 < NCC) {
            WOUT_ISSUE(nc + 1);
            cpa_wait<1>();
        } else {
            cpa_wait<0>();
        }
        __syncthreads();
        int buf = nc & 1;
        const bf16* b_base = B_s + buf * (64 * WB_STRIDE);

        wmma::fragment<wmma::accumulator, 16, 16, 16, float> acc[2];
        wmma::fill_fragment(acc[0], 0.0f);
        wmma::fill_fragment(acc[1], 0.0f);
#pragma unroll
        for (int kk = 0; kk < 16; kk++) {
            wmma::fragment<wmma::matrix_a, 16, 16, 16, bf16, wmma::row_major> af[2];
            wmma::fragment<wmma::matrix_b, 16, 16, 16, bf16, wmma::col_major> bfr;
            wmma::load_matrix_sync(af[0], A_s + (wm * 32) * WA_STRIDE + kk * 16, WA_STRIDE);
            wmma::load_matrix_sync(af[1], A_s + (wm * 32 + 16) * WA_STRIDE + kk * 16, WA_STRIDE);
            wmma::load_matrix_sync(bfr, b_base + (wn * 16) * WB_STRIDE + kk * 16, WB_STRIDE);
            wmma::mma_sync(acc[0], af[0], bfr, acc[0]);
            wmma::mma_sync(acc[1], af[1], bfr, acc[1]);
        }
        wmma::store_matrix_sync(C_s + (wm * 32) * 72 + wn * 16, acc[0], 72, wmma::mem_row_major);
        wmma::store_matrix_sync(C_s + (wm * 32 + 16) * 72 + wn * 16, acc[1], 72, wmma::mem_row_major);
        __syncthreads();

        {   // online logsumexp: 4 lanes per row, 16 cols each
            int n0v = nc * 64;
            int r = tid >> 2, q = tid & 3;
            float lm = -1e30f, ls = 0.f;
            int tgt = rTgt[r];
#pragma unroll
            for (int c = 0; c < 16; c++) {
                int col = q * 16 + c;
                int gcol = n0v + col;
                float l = C_s[r * 72 + col] + bout[gcol];
                if (gcol == 2) rE[r] = l;
                if (gcol == tgt) rT[r] = l;
                if (l <= lm) {
                    ls += __expf(l - lm);
                } else {
                    ls = ls * __expf(lm - l) + 1.0f;
                    lm = l;
                }
            }
#pragma unroll
            for (int off = 1; off < 4; off <<= 1) {
                float om = __shfl_xor_sync(0xffffffffu, lm, off);
                float os = __shfl_xor_sync(0xffffffffu, ls, off);
                float nm = fmaxf(lm, om);
                ls = ls * __expf(lm - nm) + os * __expf(om - nm);
                lm = nm;
            }
            if (q == 0) {
                float M = rM[r], S = rS[r];
                float nm = fmaxf(M, lm);
                rS[r] = S * __expf(M - nm) + ls * __expf(lm - nm);
                rM[r] = nm;
            }
        }
        __syncthreads();
    }

    if (tid < 64) {
        int n = m0 + tid;
        float lse = rM[tid] + logf(rS[tid]);
        int j = n % JC;
        bool valid = (j + kstep) <= T2C;
        float cv = cum[n];
        outp[(size_t)n * KSEG + kstep] = valid ? (cv + rE[tid] - lse) : -1e9f;
        cum[n] = cv + rT[tid] - lse;
    }
#undef WOUT_ISSUE
}

// ---------------- host launch ----------------
static inline float* fsym(const void* sym) {
    void* p = nullptr; cudaGetSymbolAddress(&p, sym); return (float*)p;
}
static inline bf16* bsym(const void* sym) {
    void* p = nullptr; cudaGetSymbolAddress(&p, sym); return (bf16*)p;
}
static inline int* isym(const void* sym) {
    void* p = nullptr; cudaGetSymbolAddress(&p, sym); return (int*)p;
}

extern "C" void kernel_launch(void* const* d_in, const int* in_sizes, int n_in,
                              void* d_out, int out_size) {
    const int*   prev   = (const int*)d_in[0];
    const float* encO   = (const float*)d_in[1];
    const float* encH   = (const float*)d_in[2];
    const float* encC   = (const float*)d_in[3];
    const float* embed  = (const float*)d_in[4];
    const float* Wph    = (const float*)d_in[5];
    const float* bph    = (const float*)d_in[6];
    const float* Wpc    = (const float*)d_in[7];
    const float* bpc    = (const float*)d_in[8];
    const float* Wih0   = (const float*)d_in[9];
    const float* Whh1   = (const float*)d_in[14];
    const float* Wih1   = (const float*)d_in[13];
    const float* bih0   = (const float*)d_in[11];
    const float* bhh0   = (const float*)d_in[12];
    const float* Whh0   = (const float*)d_in[10];
    const float* bih1   = (const float*)d_in[15];
    const float* bhh1   = (const float*)d_in[16];
    const float* Wfc    = (const float*)d_in[17];
    const float* bfc    = (const float*)d_in[18];
    const float* Wout   = (const float*)d_in[19];
    const float* bout   = (const float*)d_in[20];
    float* outp = (float*)d_out;

    bf16*  pX1   = bsym(d_X1);
    float* pg    = fsym(d_g);
    float* pc0   = fsym(d_c0);
    float* pc1   = fsym(d_c1);
    bf16*  pfco  = bsym(d_fco);
    float* pgin  = fsym(d_gin);
    float* pgctx = fsym(d_gctx);
    bf16*  pctxb = bsym(d_ctxb);
    float* pcum  = fsym(d_cum);
    int*   pgoff = isym(d_ginoff);
    int*   pcoff = isym(d_ctxoff);
    int*   ptgt  = isym(d_tgttok);
    bf16*  pWhh0b  = bsym(d_Whh0b);
    bf16*  pW1catb = bsym(d_W1catb);
    bf16*  pWfcb   = bsym(d_Wfcb);
    bf16*  pWoutb  = bsym(d_Woutb);
    bf16*  pembb   = bsym(d_embb);
    bf16*  pWih0b  = bsym(d_Wih0b);
    bf16*  pWphb   = bsym(d_Wphb);
    bf16*  pencOb  = bsym(d_encOb);

    // one-time attribute setup (idempotent)
    cudaFuncSetAttribute(gemm_bf<0, true,  false>, cudaFuncAttributeMaxDynamicSharedMemorySize, GSM_BYTES);
    cudaFuncSetAttribute(gemm_bf<1, true,  true >, cudaFuncAttributeMaxDynamicSharedMemorySize, GSM_BYTES);
    cudaFuncSetAttribute(gemm_bf<1, false, true >, cudaFuncAttributeMaxDynamicSharedMemorySize, GSM_BYTES);
    cudaFuncSetAttribute(gemm_bf<2, false, false>, cudaFuncAttributeMaxDynamicSharedMemorySize, GSM_BYTES);
    cudaFuncSetAttribute(gemm_bf<3, false, false>, cudaFuncAttributeMaxDynamicSharedMemorySize, GSM_BYTES);
    cudaFuncSetAttribute(wout_lse, cudaFuncAttributeMaxDynamicSharedMemorySize, WOUT_SMEM_BYTES);

    // ---- prologue: conversions ----
    cvt_kernel<<<(GHC * HC / 4 + 255) / 256, 256>>>(Whh0, pWhh0b, GHC * HC / 4);
    w1cat_kernel<<<(GHC * 1024 + 255) / 256, 256>>>(Wih1, Whh1);
    cvt_kernel<<<(EC * HC / 4 + 255) / 256, 256>>>(Wfc, pWfcb, EC * HC / 4);
    cvt_kernel<<<(VC * EC / 4 + 255) / 256, 256>>>(Wout, pWoutb, VC * EC / 4);
    cvt_kernel<<<((VC + 2) * EC / 4 + 255) / 256, 256>>>(embed, pembb, (VC + 2) * EC / 4);
    cvt_kernel<<<(GHC * (EC + HC) / 4 + 255) / 256, 256>>>(Wih0, pWih0b, GHC * (EC + HC) / 4);
    cvt_kernel<<<(HC * UC / 4 + 255) / 256, 256>>>(Wph, pWphb, HC * UC / 4);
    cvt_kernel<<<(T1C * BB * UC / 4 + 255) / 256, 256>>>(encO, pencOb, T1C * BB * UC / 4);

    tok_kernel<<<(GIN_ROWS_PAD + 255) / 256, 256>>>(prev);
    ctxoff_kernel<<<1, 256>>>();
    hcinit_kernel<<<(2 * BB * HC + 255) / 256, 256>>>(encH, encC, Wph, bph, Wpc, bpc);
    initX_kernel<<<(NN * HC) / 256, 256>>>();

    // ctx(bf16) = encO @ Wph^T + bph : M=256, N=512, K=1024 (gathered A)
    gemm_bf<1, true, true><<<dim3(512 / 128, 256 / 128), 256, GSM_BYTES>>>(
        pencOb, 0, pWphb, UC, pctxb, HC, UC, pcoff, bph, nullptr, 0);
    // gctx = ctx @ Wih0[:,E:]^T + bih0 + bhh0 : M=256, N=2048, K=512
    gemm_bf<2, false, false><<<dim3(GHC / 128, 256 / 128), 256, GSM_BYTES>>>(
        pctxb, HC, pWih0b + EC, EC + HC, pgctx, GHC, HC, nullptr, bih0, bhh0, 0);
    // gin = emb @ Wih0[:, :E]^T : M=2432, N=2048, K=256 (gathered A)
    gemm_bf<0, true, false><<<dim3(GHC / 128, GIN_ROWS_PAD / 128), 256, GSM_BYTES>>>(
        pembb, 0, pWih0b, EC + HC, pgin, GHC, EC, pgoff, nullptr, nullptr, 0);

    for (int k = 0; k < KSEG; k++) {
        // g0 = h0 @ Whh0^T + gin + gctx
        gemm_bf<3, false, false><<<dim3(GHC / 128, NN / 128), 256, GSM_BYTES>>>(
            pX1, 1024, pWhh0b, HC, pg, GHC, HC, nullptr, pgin, pgctx, k);
        cell_kernel<<<(NN * HC) / 256, 256>>>(pg, pc0, pX1);
        // g1 = [h0n|h1] @ [Wih1|Whh1]^T + bih1 + bhh1
        gemm_bf<2, false, false><<<dim3(GHC / 128, NN / 128), 256, GSM_BYTES>>>(
            pX1, 1024, pW1catb, 1024, pg, GHC, 1024, nullptr, bih1, bhh1, 0);
        cell_kernel<<<(NN * HC) / 256, 256>>>(pg, pc1, pX1 + 512);
        // fco(bf16) = h1 @ Wfc^T + bfc
        gemm_bf<1, false, true><<<dim3(EC / 128, NN / 128), 256, GSM_BYTES>>>(
            pX1 + 512, 1024, pWfcb, HC, pfco, EC, HC, nullptr, bfc, nullptr, 0);
        // fused logits + logsumexp + output + cum update
        wout_lse<<<NN / 64, 256, WOUT_SMEM_BYTES>>>(pfco, pWoutb, bout, ptgt, pcum, outp, k);
    }
}

// round 3
// speedup vs baseline: 3.5288x; 1.1320x over previous
#include <cuda_runtime.h>
#include <cuda_bf16.h>
#include <mma.h>
#include <math.h>
#include <stdint.h>

using namespace nvcuda;

// ---------------- problem constants ----------------
#define BB 8
#define T1C 32
#define T2C 32
#define JC 33          // T2+1
#define KSEG 9         // MAXSEG+1
#define NN 8448        // B*T1*J
#define EC 256
#define HC 512
#define UC 1024
#define GHC 2048       // 4*H
#define VC 8000
#define START_ID 8001
#define GIN_ROWS 2376
#define GIN_ROWS_PAD 2432

typedef __nv_bfloat16 bf16;
typedef __nv_bfloat162 bf162;

// ---------------- device scratch ----------------
__device__ bf16  d_X1[NN * 1024];          // [h0 | h1] per row (bf16)
__device__ float d_c0[NN * HC];
__device__ float d_c1[NN * HC];
__device__ bf16  d_fco[NN * EC];
__device__ float d_gin[GIN_ROWS_PAD * GHC];   // permuted gate cols
__device__ float d_gctx[256 * GHC];           // permuted gate cols (incl. b0)
__device__ bf16  d_ctxb[256 * HC];
__device__ float d_hinit[2 * BB * HC];
__device__ float d_cinit[2 * BB * HC];
__device__ float d_cum[NN];
__device__ float d_b0p[GHC];                  // permuted bih0+bhh0
__device__ float d_b1p[GHC];                  // permuted bih1+bhh1
__device__ int   d_ginoff[GIN_ROWS_PAD];
__device__ int   d_ctxoff[256];
__device__ int   d_tgttok[GIN_ROWS];
// bf16 weight copies (LSTM weights row-permuted to [h*4+gate])
__device__ bf16 d_Whh0b[GHC * HC];
__device__ bf16 d_W1catb[GHC * 1024];
__device__ bf16 d_Wfcb[EC * HC];
__device__ bf16 d_Woutb[VC * EC];
__device__ bf16 d_embb[(VC + 2) * EC];
__device__ bf16 d_Wih0b[GHC * (EC + HC)];     // row-permuted
__device__ bf16 d_Wphb[HC * UC];
__device__ bf16 d_encOb[T1C * BB * UC];

__device__ __forceinline__ float tanha(float x) {
    float y; asm("tanh.approx.f32 %0, %1;" : "=f"(y) : "f"(x)); return y;
}
__device__ __forceinline__ float sigfast(float x) { return 0.5f * tanha(0.5f * x) + 0.5f; }

__device__ __forceinline__ void cpa16(void* dst, const void* src) {
    uint32_t d = (uint32_t)__cvta_generic_to_shared(dst);
    asm volatile("cp.async.cg.shared.global [%0], [%1], 16;\n" :: "r"(d), "l"(src));
}
__device__ __forceinline__ void cpa_commit() { asm volatile("cp.async.commit_group;\n"); }
template <int N> __device__ __forceinline__ void cpa_wait() {
    asm volatile("cp.async.wait_group %0;\n" :: "n"(N));
}

// ---------------- prologue kernels ----------------
__global__ void cvt_kernel(const float* __restrict__ src, bf16* __restrict__ dst, int n4) {
    int i = blockIdx.x * blockDim.x + threadIdx.x;
    if (i >= n4) return;
    float4 v = ((const float4*)src)[i];
    bf162* d = (bf162*)dst + i * 2;
    d[0] = __floats2bfloat162_rn(v.x, v.y);
    d[1] = __floats2bfloat162_rn(v.z, v.w);
}

// permuted convert: dst[(h*4+gate)*ldw + c] = W[(gate*512+h)*ldw + c]
__global__ void wperm_kernel(const float* __restrict__ W, bf16* __restrict__ dst, int ldw) {
    int idx = blockIdx.x * blockDim.x + threadIdx.x;
    if (idx >= GHC * ldw) return;
    int np = idx / ldw, c = idx - np * ldw;
    int h = np >> 2, gate = np & 3;
    dst[idx] = __float2bfloat16(W[(size_t)(gate * HC + h) * ldw + c]);
}

__global__ void w1catperm_kernel(const float* __restrict__ Wih1, const float* __restrict__ Whh1) {
    int idx = blockIdx.x * blockDim.x + threadIdx.x;
    if (idx >= GHC * 1024) return;
    int np = idx >> 10, c = idx & 1023;
    int o = (np & 3) * HC + (np >> 2);
    float v = (c < HC) ? Wih1[(size_t)o * HC + c] : Whh1[(size_t)o * HC + (c - HC)];
    d_W1catb[idx] = __float2bfloat16(v);
}

__global__ void biasperm_kernel(const float* __restrict__ bih0, const float* __restrict__ bhh0,
                                const float* __restrict__ bih1, const float* __restrict__ bhh1) {
    int idx = blockIdx.x * blockDim.x + threadIdx.x;
    if (idx >= GHC) return;
    int o = (idx & 3) * HC + (idx >> 2);
    d_b0p[idx] = bih0[o] + bhh0[o];
    d_b1p[idx] = bih1[o] + bhh1[o];
}

__global__ void tok_kernel(const int* __restrict__ prev) {
    int r = blockIdx.x * blockDim.x + threadIdx.x;
    if (r >= GIN_ROWS_PAD) return;
    if (r < GIN_ROWS) {
        int k = r / (BB * JC);
        int bj = r - k * (BB * JC);
        int b = bj / JC;
        int j = bj - b * JC;
        int pin = j + k - 1; if (pin > T2C - 1) pin = T2C - 1;
        int tin = (k == 0) ? START_ID : prev[b * T2C + pin];
        d_ginoff[r] = tin * EC;
        int pt = j + k; if (pt > T2C - 1) pt = T2C - 1;
        d_tgttok[r] = prev[b * T2C + pt];
    } else {
        d_ginoff[r] = 0;
    }
}

__global__ void ctxoff_kernel() {
    int r = threadIdx.x;
    if (r < 256) {
        int b = r / T1C, t1 = r - b * T1C;
        d_ctxoff[r] = t1 * (BB * UC) + b * UC;
    }
}

__global__ void hcinit_kernel(const float* __restrict__ ench, const float* __restrict__ encc,
                              const float* __restrict__ Wph, const float* __restrict__ bph,
                              const float* __restrict__ Wpc, const float* __restrict__ bpc) {
    int idx = blockIdx.x * blockDim.x + threadIdx.x;
    if (idx >= 2 * BB * HC) return;
    int l = idx / (BB * HC);
    int b = (idx / HC) % BB;
    int h = idx % HC;
    const float4* eh = (const float4*)(ench + l * BB * UC + b * UC);
    const float4* ec = (const float4*)(encc + l * BB * UC + b * UC);
    const float4* wh = (const float4*)(Wph + (size_t)h * UC);
    const float4* wc = (const float4*)(Wpc + (size_t)h * UC);
    float sh = 0.f, sc = 0.f;
    for (int u = 0; u < UC / 4; u++) {
        float4 a = eh[u], w = wh[u];
        sh += a.x * w.x + a.y * w.y + a.z * w.z + a.w * w.w;
        float4 a2 = ec[u], w2 = wc[u];
        sc += a2.x * w2.x + a2.y * w2.y + a2.z * w2.z + a2.w * w2.w;
    }
    d_hinit[idx] = sh + bph[h];
    d_cinit[idx] = sc + bpc[h];
}

__global__ void initX_kernel() {
    int idx = blockIdx.x * blockDim.x + threadIdx.x;
    if (idx >= NN * HC) return;
    int n = idx >> 9, h = idx & 511;
    int b = n / (T1C * JC);
    d_X1[(size_t)n * 1024 + h]       = __float2bfloat16(d_hinit[b * HC + h]);
    d_X1[(size_t)n * 1024 + 512 + h] = __float2bfloat16(d_hinit[BB * HC + b * HC + h]);
    d_c0[idx] = d_cinit[b * HC + h];
    d_c1[idx] = d_cinit[BB * HC + b * HC + h];
    if (h == 0) d_cum[n] = 0.f;
}

// ---------------- bf16 TN GEMM, 128x128 tiles, single-sync 2-stage pipeline ----------
// EPI: 0 none, 1 +e1[n], 4 CELL0 (+gin+gctx then LSTM cell), 5 CELL1 (+e1[n] then cell)
#define SASTRIDE 40
#define GSM_BYTES 67584    // sC overlay 128*132*4 dominates
template <int EPI, bool GATHER, bool OBF>
__launch_bounds__(256)
__global__ void gemm_bf(const bf16* __restrict__ A, int lda,
                        const bf16* __restrict__ Bm, int ldb,
                        void* __restrict__ Cv, int ldc, int K,
                        const int* __restrict__ rowoff,
                        const float* __restrict__ e1, const float* __restrict__ e2,
                        int kstep, float* __restrict__ cptr, bf16* __restrict__ hout) {
    extern __shared__ char smraw[];
    bf16* sA = (bf16*)smraw;                  // [2][128*40]
    bf16* sB = sA + 2 * 128 * SASTRIDE;       // [2][128*40]
    float* sC = (float*)smraw;                // 128*132 overlay

    int tid = threadIdx.x;
    int m0 = blockIdx.y * 128, n0 = blockIdx.x * 128;
    int wid = tid >> 5;
    int wm = wid & 1, wn = wid >> 1;          // warp tile 64(m) x 32(n)

    wmma::fragment<wmma::accumulator, 16, 16, 16, float> acc[4][2];
#pragma unroll
    for (int mi = 0; mi < 4; mi++)
#pragma unroll
        for (int ni = 0; ni < 2; ni++) wmma::fill_fragment(acc[mi][ni], 0.0f);

    int nk = K >> 5;

#define GEMM_ISSUE(S)                                                                    \
    {                                                                                    \
        int buf_ = (S) & 1;                                                              \
        int k0_ = (S) << 5;                                                              \
        _Pragma("unroll")                                                                \
        for (int i_ = 0; i_ < 2; i_++) {                                                 \
            int idx_ = tid + i_ * 256;                                                   \
            int r_ = idx_ >> 2, c_ = idx_ & 3;                                           \
            const bf16* src_ = GATHER ? (A + rowoff[m0 + r_] + k0_ + c_ * 8)             \
                                      : (A + (size_t)(m0 + r_) * lda + k0_ + c_ * 8);    \
            cpa16(sA + buf_ * (128 * SASTRIDE) + r_ * SASTRIDE + c_ * 8, src_);          \
        }                                                                                \
        _Pragma("unroll")                                                                \
        for (int i_ = 0; i_ < 2; i_++) {                                                 \
            int idx_ = tid + i_ * 256;                                                   \
            int r_ = idx_ >> 2, c_ = idx_ & 3;                                           \
            cpa16(sB + buf_ * (128 * SASTRIDE) + r_ * SASTRIDE + c_ * 8,                 \
                  Bm + (size_t)(n0 + r_) * ldb + k0_ + c_ * 8);                          \
        }                                                                                \
        cpa_commit();                                                                    \
    }

    GEMM_ISSUE(0);
    for (int s = 0; s < nk; s++) {
        cpa_wait<0>();
        __syncthreads();
        if (s + 1 < nk) GEMM_ISSUE(s + 1);
        int buf = s & 1;
        const bf16* a_base = sA + buf * (128 * SASTRIDE);
        const bf16* b_base = sB + buf * (128 * SASTRIDE);
#pragma unroll
        for (int kk = 0; kk < 2; kk++) {
            wmma::fragment<wmma::matrix_a, 16, 16, 16, bf16, wmma::row_major> af[4];
            wmma::fragment<wmma::matrix_b, 16, 16, 16, bf16, wmma::col_major> bfr[2];
#pragma unroll
            for (int mi = 0; mi < 4; mi++)
                wmma::load_matrix_sync(af[mi], a_base + (wm * 64 + mi * 16) * SASTRIDE + kk * 16, SASTRIDE);
#pragma unroll
            for (int ni = 0; ni < 2; ni++)
                wmma::load_matrix_sync(bfr[ni], b_base + (wn * 32 + ni * 16) * SASTRIDE + kk * 16, SASTRIDE);
#pragma unroll
            for (int mi = 0; mi < 4; mi++)
#pragma unroll
                for (int ni = 0; ni < 2; ni++)
                    wmma::mma_sync(acc[mi][ni], af[mi], bfr[ni], acc[mi][ni]);
        }
    }
    __syncthreads();
#pragma unroll
    for (int mi = 0; mi < 4; mi++)
#pragma unroll
        for (int ni = 0; ni < 2; ni++)
            wmma::store_matrix_sync(sC + (wm * 64 + mi * 16) * 132 + wn * 32 + ni * 16,
                                    acc[mi][ni], 132, wmma::mem_row_major);
    __syncthreads();

#pragma unroll
    for (int i = 0; i < 16; i++) {
        int idx = tid + i * 256;
        int r = idx >> 5, c4 = idx & 31;
        float4 v = *(float4*)(sC + r * 132 + c4 * 4);
        int m = m0 + r;
        int nb = n0 + c4 * 4;
        if (EPI == 1 || EPI == 5) {
            float4 bb = *(const float4*)(e1 + nb);
            v.x += bb.x; v.y += bb.y; v.z += bb.z; v.w += bb.w;
        }
        if (EPI == 4) {
            int b = m / (T1C * JC);
            int rem = m - b * (T1C * JC);
            int t1 = rem / JC;
            int j = rem - t1 * JC;
            const float* gi = e1 + (size_t)((kstep * BB + b) * JC + j) * GHC + nb;
            const float* gc = e2 + (size_t)(b * T1C + t1) * GHC + nb;
            float4 a1 = *(const float4*)gi;
            float4 a2 = *(const float4*)gc;
            v.x += a1.x + a2.x; v.y += a1.y + a2.y; v.z += a1.z + a2.z; v.w += a1.w + a2.w;
        }
        if (EPI == 4 || EPI == 5) {
            // v = (i, f, g, o) for h = nb>>2
            int h = nb >> 2;
            size_t cix = (size_t)m * HC + h;
            float cold = cptr[cix];
            float cn = sigfast(v.y) * cold + sigfast(v.x) * tanha(v.z);
            cptr[cix] = cn;
            hout[(size_t)m * 1024 + h] = __float2bfloat16(sigfast(v.w) * tanha(cn));
        } else if (OBF) {
            bf162* p = (bf162*)((bf16*)Cv + (size_t)m * ldc + nb);
            p[0] = __floats2bfloat162_rn(v.x, v.y);
            p[1] = __floats2bfloat162_rn(v.z, v.w);
        } else {
            *(float4*)((float*)Cv + (size_t)m * ldc + nb) = v;
        }
    }
#undef GEMM_ISSUE
}

// ---------------- fused Wout GEMM (bf16) + online logsumexp ----------------
#define WA_STRIDE 264
#define WB_STRIDE 264
#define WOUT_SMEM_BYTES (64 * WA_STRIDE * 2 + 2 * 64 * WB_STRIDE * 2 + 64 * 72 * 4 + 64 * 5 * 4)
__launch_bounds__(256)
__global__ void wout_lse(const bf16* __restrict__ fco, const bf16* __restrict__ Wout,
                         const float* __restrict__ bout, const int* __restrict__ tgttok,
                         float* __restrict__ cum, float* __restrict__ outp, int kstep) {
    extern __shared__ char smraw[];
    bf16* A_s = (bf16*)smraw;                         // 64 x 264
    bf16* B_s = A_s + 64 * WA_STRIDE;                 // 2 x 64 x 264
    float* C_s = (float*)(B_s + 2 * 64 * WB_STRIDE);  // 64 x 72
    float* rM = C_s + 64 * 72;
    float* rS = rM + 64;
    float* rE = rS + 64;
    float* rT = rE + 64;
    int* rTgt = (int*)(rT + 64);

    int tid = threadIdx.x;
    int m0 = blockIdx.x * 64;

#pragma unroll
    for (int i = 0; i < 8; i++) {
        int idx = tid + i * 256;
        int r = idx >> 5, c = idx & 31;
        *(uint4*)(A_s + r * WA_STRIDE + c * 8) = *(const uint4*)(fco + (size_t)(m0 + r) * EC + c * 8);
    }
    if (tid < 64) {
        int n = m0 + tid;
        int b = n / (T1C * JC);
        int rem = n - b * (T1C * JC);
        int j = rem % JC;
        rTgt[tid] = tgttok[(kstep * BB + b) * JC + j];
        rM[tid] = -1e30f; rS[tid] = 0.f; rE[tid] = 0.f; rT[tid] = 0.f;
    }

    int wid = tid >> 5;
    int wm = wid & 1, wn = wid >> 1;

#define WOUT_ISSUE(S)                                                                  \
    {                                                                                  \
        int buf_ = (S) & 1;                                                            \
        _Pragma("unroll")                                                              \
        for (int i_ = 0; i_ < 8; i_++) {                                               \
            int idx_ = tid + i_ * 256;                                                 \
            int r_ = idx_ >> 5, c_ = idx_ & 31;                                        \
            cpa16(B_s + buf_ * (64 * WB_STRIDE) + r_ * WB_STRIDE + c_ * 8,             \
                  Wout + (size_t)((S) * 64 + r_) * EC + c_ * 8);                       \
        }                                                                              \
        cpa_commit();                                                                  \
    }

    WOUT_ISSUE(0);
    const int NCC = VC / 64;  // 125
    for (int nc = 0; nc < NCC; nc++) {
        cpa_wait<0>();
        __syncthreads();
        if (nc + 1 < NCC) WOUT_ISSUE(nc + 1);
        int buf = nc & 1;
        const bf16* b_base = B_s + buf * (64 * WB_STRIDE);

        wmma::fragment<wmma::accumulator, 16, 16, 16, float> acc[2];
        wmma::fill_fragment(acc[0], 0.0f);
        wmma::fill_fragment(acc[1], 0.0f);
#pragma unroll
        for (int kk = 0; kk < 16; kk++) {
            wmma::fragment<wmma::matrix_a, 16, 16, 16, bf16, wmma::row_major> af[2];
            wmma::fragment<wmma::matrix_b, 16, 16, 16, bf16, wmma::col_major> bfr;
            wmma::load_matrix_sync(af[0], A_s + (wm * 32) * WA_STRIDE + kk * 16, WA_STRIDE);
            wmma::load_matrix_sync(af[1], A_s + (wm * 32 + 16) * WA_STRIDE + kk * 16, WA_STRIDE);
            wmma::load_matrix_sync(bfr, b_base + (wn * 16) * WB_STRIDE + kk * 16, WB_STRIDE);
            wmma::mma_sync(acc[0], af[0], bfr, acc[0]);
            wmma::mma_sync(acc[1], af[1], bfr, acc[1]);
        }
        wmma::store_matrix_sync(C_s + (wm * 32) * 72 + wn * 16, acc[0], 72, wmma::mem_row_major);
        wmma::store_matrix_sync(C_s + (wm * 32 + 16) * 72 + wn * 16, acc[1], 72, wmma::mem_row_major);
        __syncthreads();

        {   // two-pass logsumexp over this 64-col chunk: 4 lanes per row, 16 cols each
            int n0v = nc * 64;
            int r = tid >> 2, q = tid & 3;
            int tgt = rTgt[r];
            float lv[16];
            float lm = -1e30f;
#pragma unroll
            for (int c = 0; c < 16; c++) {
                int col = q * 16 + c;
                int gcol = n0v + col;
                float l = C_s[r * 72 + col] + bout[gcol];
                lv[c] = l;
                lm = fmaxf(lm, l);
                if (gcol == 2) rE[r] = l;
                if (gcol == tgt) rT[r] = l;
            }
            float ls = 0.f;
#pragma unroll
            for (int c = 0; c < 16; c++) ls += __expf(lv[c] - lm);
#pragma unroll
            for (int off = 1; off < 4; off <<= 1) {
                float om = __shfl_xor_sync(0xffffffffu, lm, off);
                float os = __shfl_xor_sync(0xffffffffu, ls, off);
                float nm = fmaxf(lm, om);
                ls = ls * __expf(lm - nm) + os * __expf(om - nm);
                lm = nm;
            }
            if (q == 0) {
                float M = rM[r], S = rS[r];
                float nm = fmaxf(M, lm);
                rS[r] = S * __expf(M - nm) + ls * __expf(lm - nm);
                rM[r] = nm;
            }
        }
        __syncthreads();
    }

    if (tid < 64) {
        int n = m0 + tid;
        float lse = rM[tid] + logf(rS[tid]);
        int j = n % JC;
        bool valid = (j + kstep) <= T2C;
        float cv = cum[n];
        outp[(size_t)n * KSEG + kstep] = valid ? (cv + rE[tid] - lse) : -1e9f;
        cum[n] = cv + rT[tid] - lse;
    }
#undef WOUT_ISSUE
}

// ---------------- host launch ----------------
static inline float* fsym(const void* sym) {
    void* p = nullptr; cudaGetSymbolAddress(&p, sym); return (float*)p;
}
static inline bf16* bsym(const void* sym) {
    void* p = nullptr; cudaGetSymbolAddress(&p, sym); return (bf16*)p;
}
static inline int* isym(const void* sym) {
    void* p = nullptr; cudaGetSymbolAddress(&p, sym); return (int*)p;
}

extern "C" void kernel_launch(void* const* d_in, const int* in_sizes, int n_in,
                              void* d_out, int out_size) {
    const int*   prev   = (const int*)d_in[0];
    const float* encO   = (const float*)d_in[1];
    const float* encH   = (const float*)d_in[2];
    const float* encC   = (const float*)d_in[3];
    const float* embed  = (const float*)d_in[4];
    const float* Wph    = (const float*)d_in[5];
    const float* bph    = (const float*)d_in[6];
    const float* Wpc    = (const float*)d_in[7];
    const float* bpc    = (const float*)d_in[8];
    const float* Wih0   = (const float*)d_in[9];
    const float* Whh0   = (const float*)d_in[10];
    const float* bih0   = (const float*)d_in[11];
    const float* bhh0   = (const float*)d_in[12];
    const float* Wih1   = (const float*)d_in[13];
    const float* Whh1   = (const float*)d_in[14];
    const float* bih1   = (const float*)d_in[15];
    const float* bhh1   = (const float*)d_in[16];
    const float* Wfc    = (const float*)d_in[17];
    const float* bfc    = (const float*)d_in[18];
    const float* Wout   = (const float*)d_in[19];
    const float* bout   = (const float*)d_in[20];
    float* outp = (float*)d_out;

    bf16*  pX1   = bsym(d_X1);
    float* pc0   = fsym(d_c0);
    float* pc1   = fsym(d_c1);
    bf16*  pfco  = bsym(d_fco);
    float* pgin  = fsym(d_gin);
    float* pgctx = fsym(d_gctx);
    bf16*  pctxb = bsym(d_ctxb);
    float* pcum  = fsym(d_cum);
    float* pb0p  = fsym(d_b0p);
    float* pb1p  = fsym(d_b1p);
    int*   pgoff = isym(d_ginoff);
    int*   pcoff = isym(d_ctxoff);
    int*   ptgt  = isym(d_tgttok);
    bf16*  pWhh0b  = bsym(d_Whh0b);
    bf16*  pW1catb = bsym(d_W1catb);
    bf16*  pWfcb   = bsym(d_Wfcb);
    bf16*  pWoutb  = bsym(d_Woutb);
    bf16*  pembb   = bsym(d_embb);
    bf16*  pWih0b  = bsym(d_Wih0b);
    bf16*  pWphb   = bsym(d_Wphb);
    bf16*  pencOb  = bsym(d_encOb);

    cudaFuncSetAttribute(gemm_bf<0, true,  false>, cudaFuncAttributeMaxDynamicSharedMemorySize, GSM_BYTES);
    cudaFuncSetAttribute(gemm_bf<1, true,  true >, cudaFuncAttributeMaxDynamicSharedMemorySize, GSM_BYTES);
    cudaFuncSetAttribute(gemm_bf<1, false, false>, cudaFuncAttributeMaxDynamicSharedMemorySize, GSM_BYTES);
    cudaFuncSetAttribute(gemm_bf<1, false, true >, cudaFuncAttributeMaxDynamicSharedMemorySize, GSM_BYTES);
    cudaFuncSetAttribute(gemm_bf<4, false, false>, cudaFuncAttributeMaxDynamicSharedMemorySize, GSM_BYTES);
    cudaFuncSetAttribute(gemm_bf<5, false, false>, cudaFuncAttributeMaxDynamicSharedMemorySize, GSM_BYTES);
    cudaFuncSetAttribute(wout_lse, cudaFuncAttributeMaxDynamicSharedMemorySize, WOUT_SMEM_BYTES);

    // ---- prologue: conversions / permutations ----
    wperm_kernel<<<(GHC * HC + 255) / 256, 256>>>(Whh0, pWhh0b, HC);
    w1catperm_kernel<<<(GHC * 1024 + 255) / 256, 256>>>(Wih1, Whh1);
    wperm_kernel<<<(GHC * (EC + HC) + 255) / 256, 256>>>(Wih0, pWih0b, EC + HC);
    biasperm_kernel<<<(GHC + 255) / 256, 256>>>(bih0, bhh0, bih1, bhh1);
    cvt_kernel<<<(EC * HC / 4 + 255) / 256, 256>>>(Wfc, pWfcb, EC * HC / 4);
    cvt_kernel<<<(VC * EC / 4 + 255) / 256, 256>>>(Wout, pWoutb, VC * EC / 4);
    cvt_kernel<<<((VC + 2) * EC / 4 + 255) / 256, 256>>>(embed, pembb, (VC + 2) * EC / 4);
    cvt_kernel<<<(HC * UC / 4 + 255) / 256, 256>>>(Wph, pWphb, HC * UC / 4);
    cvt_kernel<<<(T1C * BB * UC / 4 + 255) / 256, 256>>>(encO, pencOb, T1C * BB * UC / 4);

    tok_kernel<<<(GIN_ROWS_PAD + 255) / 256, 256>>>(prev);
    ctxoff_kernel<<<1, 256>>>();
    hcinit_kernel<<<(2 * BB * HC + 255) / 256, 256>>>(encH, encC, Wph, bph, Wpc, bpc);
    initX_kernel<<<(NN * HC) / 256, 256>>>();

    // ctx(bf16) = encO @ Wph^T + bph : M=256, N=512, K=1024 (gathered A)
    gemm_bf<1, true, true><<<dim3(512 / 128, 256 / 128), 256, GSM_BYTES>>>(
        pencOb, 0, pWphb, UC, pctxb, HC, UC, pcoff, bph, nullptr, 0, nullptr, nullptr);
    // gctx = ctx @ Wih0p[:,E:]^T + b0p : M=256, N=2048(perm), K=512
    gemm_bf<1, false, false><<<dim3(GHC / 128, 256 / 128), 256, GSM_BYTES>>>(
        pctxb, HC, pWih0b + EC, EC + HC, pgctx, GHC, HC, nullptr, pb0p, nullptr, 0, nullptr, nullptr);
    // gin = emb @ Wih0p[:, :E]^T : M=2432, N=2048(perm), K=256 (gathered A)
    gemm_bf<0, true, false><<<dim3(GHC / 128, GIN_ROWS_PAD / 128), 256, GSM_BYTES>>>(
        pembb, 0, pWih0b, EC + HC, pgin, GHC, EC, pgoff, nullptr, nullptr, 0, nullptr, nullptr);

    for (int k = 0; k < KSEG; k++) {
        // layer 0: g0 = h0 @ Whh0p^T + gin + gctx, fused cell -> c0, h0
        gemm_bf<4, false, false><<<dim3(GHC / 128, NN / 128), 256, GSM_BYTES>>>(
            pX1, 1024, pWhh0b, HC, nullptr, 0, HC, nullptr, pgin, pgctx, k, pc0, pX1);
        // layer 1: g1 = [h0|h1] @ W1catp^T + b1p, fused cell -> c1, h1
        gemm_bf<5, false, false><<<dim3(GHC / 128, NN / 128), 256, GSM_BYTES>>>(
            pX1, 1024, pW1catb, 1024, nullptr, 0, 1024, nullptr, pb1p, nullptr, k, pc1, pX1 + 512);
        // fco(bf16) = h1 @ Wfc^T + bfc
        gemm_bf<1, false, true><<<dim3(EC / 128, NN / 128), 256, GSM_BYTES>>>(
            pX1 + 512, 1024, pWfcb, HC, pfco, EC, HC, nullptr, bfc, nullptr, 0, nullptr, nullptr);
        // fused logits + logsumexp + output + cum update
        wout_lse<<<NN / 64, 256, WOUT_SMEM_BYTES>>>(pfco, pWoutb, bout, ptgt, pcum, outp, k);
    }
}